// round 1
// baseline (speedup 1.0000x reference)
#include <cuda_runtime.h>

// Problem constants: imgs (B,L,M,C,H,W) f32, ts2img_weights (B,L,M) f32
// out (B,L,K,H,W) f32 with out[b,l,k] = s * imgs[b,l,topk_idx(k),0],
// s = (1 - w_sel) + w_sel  (forward of the straight-through mask).
// Non-selected terms are exactly zero: (0 - w) + w == 0.0f in IEEE.

#define B_ 32
#define L_ 7
#define M_ 6
#define C_ 3
#define H_ 128
#define W_ 128
#define K_ 3
#define HW_ (H_ * W_)              // 16384 floats per slice
#define CHUNK_ 4096                // floats per block
#define CHUNKS_PER_SLICE_ (HW_ / CHUNK_)  // 4
#define THREADS_ 256
#define VEC_ITERS_ (CHUNK_ / 4 / THREADS_) // 4 float4 per thread

__global__ __launch_bounds__(THREADS_) void mt2v_gather_kernel(
    const float* __restrict__ imgs,
    const float* __restrict__ wts,
    float* __restrict__ out)
{
    const int blk   = blockIdx.x;
    const int chunk = blk % CHUNKS_PER_SLICE_;
    const int slice = blk / CHUNKS_PER_SLICE_;   // 0 .. B*L*K-1
    const int k     = slice % K_;
    const int bl    = slice / K_;                // 0 .. B*L-1

    // Load the 6 gate weights for this (b,l). Cheap: L2/L1 hits after first block.
    float wv[M_];
#pragma unroll
    for (int m = 0; m < M_; m++) wv[m] = __ldg(&wts[bl * M_ + m]);

    // Stable top-k selection (strict > => lowest index wins ties, matching lax.top_k).
    int sel = 0;
    bool used[M_];
#pragma unroll
    for (int m = 0; m < M_; m++) used[m] = false;
#pragma unroll
    for (int kk = 0; kk <= K_ - 1; kk++) {
        float best = -3.402823466e+38f;
        int bi = 0;
#pragma unroll
        for (int m = 0; m < M_; m++) {
            if (!used[m] && wv[m] > best) { best = wv[m]; bi = m; }
        }
        used[bi] = true;
        if (kk == k) { sel = bi; }
    }

    // Forward value of the straight-through mask at the selected index.
    const float s = (1.0f - wv[sel]) + wv[sel];

    // Source: channel 0 of imgs[b,l,sel] — contiguous HW floats.
    const size_t src_base = ((size_t)bl * M_ + (size_t)sel) * (size_t)(C_ * HW_);
    const size_t dst_base = ((size_t)bl * K_ + (size_t)k) * (size_t)HW_;

    const float4* __restrict__ src =
        reinterpret_cast<const float4*>(imgs + src_base) + (size_t)chunk * (CHUNK_ / 4);
    float4* __restrict__ dst =
        reinterpret_cast<float4*>(out + dst_base) + (size_t)chunk * (CHUNK_ / 4);

    const int t = threadIdx.x;
#pragma unroll
    for (int i = 0; i < VEC_ITERS_; i++) {
        float4 v = __ldg(&src[t + i * THREADS_]);
        v.x *= s; v.y *= s; v.z *= s; v.w *= s;
        dst[t + i * THREADS_] = v;
    }
}

extern "C" void kernel_launch(void* const* d_in, const int* in_sizes, int n_in,
                              void* d_out, int out_size)
{
    const float* imgs = (const float*)d_in[0];
    const float* wts  = (const float*)d_in[1];
    float* out        = (float*)d_out;

    const int grid = B_ * L_ * K_ * CHUNKS_PER_SLICE_;  // 2688 blocks
    mt2v_gather_kernel<<<grid, THREADS_>>>(imgs, wts, out);
}

// round 2
// speedup vs baseline: 1.3008x; 1.3008x over previous
#include <cuda_runtime.h>

// imgs (B,L,M,C,H,W) f32, ts2img_weights (B,L,M) f32
// out (B,L,K,H,W) f32: out[b,l,k] = s * imgs[b,l,topk_idx(k),0],
// s = (1 - w_sel) + w_sel. Non-selected terms are exactly 0 in IEEE fp32.

#define B_ 32
#define L_ 7
#define M_ 6
#define C_ 3
#define H_ 128
#define W_ 128
#define K_ 3
#define HW_ (H_ * W_)                      // 16384 floats per slice
#define CHUNK_ 8192                        // floats per block
#define CHUNKS_PER_SLICE_ (HW_ / CHUNK_)   // 2
#define THREADS_ 256
#define VEC_ITERS_ (CHUNK_ / 4 / THREADS_) // 8 float4 per thread

__global__ __launch_bounds__(THREADS_) void mt2v_gather_kernel(
    const float* __restrict__ imgs,
    const float* __restrict__ wts,
    float* __restrict__ out)
{
    const int blk   = blockIdx.x;
    const int chunk = blk % CHUNKS_PER_SLICE_;
    const int slice = blk / CHUNKS_PER_SLICE_;   // 0 .. B*L*K-1
    const int k     = slice % K_;
    const int bl    = slice / K_;                // 0 .. B*L-1

    // Gate weights for this (b,l). L2/L1-hot after the first touch.
    float wv[M_];
#pragma unroll
    for (int m = 0; m < M_; m++) wv[m] = __ldg(&wts[bl * M_ + m]);

    // Stable top-k (strict > => lowest index wins ties, matching lax.top_k).
    int sel = 0;
    bool used[M_];
#pragma unroll
    for (int m = 0; m < M_; m++) used[m] = false;
#pragma unroll
    for (int kk = 0; kk < K_; kk++) {
        float best = -3.402823466e+38f;
        int bi = 0;
#pragma unroll
        for (int m = 0; m < M_; m++) {
            if (!used[m] && wv[m] > best) { best = wv[m]; bi = m; }
        }
        used[bi] = true;
        if (kk == k) sel = bi;
    }

    const float s = (1.0f - wv[sel]) + wv[sel];

    const size_t src_base = ((size_t)bl * M_ + (size_t)sel) * (size_t)(C_ * HW_);
    const size_t dst_base = ((size_t)bl * K_ + (size_t)k) * (size_t)HW_;

    const float4* __restrict__ src =
        reinterpret_cast<const float4*>(imgs + src_base) + (size_t)chunk * (CHUNK_ / 4);
    float4* __restrict__ dst =
        reinterpret_cast<float4*>(out + dst_base) + (size_t)chunk * (CHUNK_ / 4);

    const int t = threadIdx.x;

    // Front-batch all loads (MLP=8 per thread), then scale + store.
    float4 v[VEC_ITERS_];
#pragma unroll
    for (int i = 0; i < VEC_ITERS_; i++)
        v[i] = __ldg(&src[t + i * THREADS_]);

#pragma unroll
    for (int i = 0; i < VEC_ITERS_; i++) {
        float4 r = v[i];
        r.x *= s; r.y *= s; r.z *= s; r.w *= s;
        dst[t + i * THREADS_] = r;
    }
}

extern "C" void kernel_launch(void* const* d_in, const int* in_sizes, int n_in,
                              void* d_out, int out_size)
{
    const float* imgs = (const float*)d_in[0];
    const float* wts  = (const float*)d_in[1];
    float* out        = (float*)d_out;

    const int grid = B_ * L_ * K_ * CHUNKS_PER_SLICE_;  // 1344 blocks
    mt2v_gather_kernel<<<grid, THREADS_>>>(imgs, wts, out);
}

// round 3
// speedup vs baseline: 1.3204x; 1.0151x over previous
#include <cuda_runtime.h>
#include <cstdint>

// imgs (B,L,M,C,H,W) f32, ts2img_weights (B,L,M) f32
// out (B,L,K,H,W) f32: out[b,l,k] = s * imgs[b,l,topk_idx(k),0]
// s = (1 - w_sel) + w_sel. Non-selected straight-through terms are exactly 0.

#define B_ 32
#define L_ 7
#define M_ 6
#define C_ 3
#define H_ 128
#define W_ 128
#define K_ 3
#define HW_ (H_ * W_)                       // 16384 floats per slice
#define NSLICE_ (B_ * L_ * K_)              // 672
#define CHUNK_ 8192                         // floats per block
#define CHUNKS_PER_SLICE_ (HW_ / CHUNK_)    // 2
#define THREADS_ 256
#define VEC_ITERS_ (CHUNK_ / 4 / THREADS_)  // 8 float4 per thread

struct Desc { int off; float s; };          // src float-offset into imgs, scale
__device__ Desc g_desc[NSLICE_];

// ---- Stage 1: per-(b,l,k) top-k selection -> descriptor -------------------
__global__ void mt2v_desc_kernel(const float* __restrict__ wts)
{
    int idx = blockIdx.x * blockDim.x + threadIdx.x;   // 0 .. NSLICE_-1
    if (idx >= NSLICE_) return;
    int k  = idx % K_;
    int bl = idx / K_;

    float wv[M_];
#pragma unroll
    for (int m = 0; m < M_; m++) wv[m] = __ldg(&wts[bl * M_ + m]);

    // Stable top-k (strict > => lowest index wins ties, matching lax.top_k).
    int sel = 0;
    bool used[M_];
#pragma unroll
    for (int m = 0; m < M_; m++) used[m] = false;
#pragma unroll
    for (int kk = 0; kk < K_; kk++) {
        float best = -3.402823466e+38f;
        int bi = 0;
#pragma unroll
        for (int m = 0; m < M_; m++)
            if (!used[m] && wv[m] > best) { best = wv[m]; bi = m; }
        used[bi] = true;
        if (kk == k) sel = bi;
    }

    Desc d;
    d.off = (bl * M_ + sel) * (C_ * HW_);   // channel 0 of imgs[b,l,sel]
    d.s   = (1.0f - wv[sel]) + wv[sel];
    g_desc[idx] = d;
}

// ---- Stage 2: scaled slice copy, forced 8-deep LDG.128 batching -----------
__global__ __launch_bounds__(THREADS_) void mt2v_gather_kernel(
    const float* __restrict__ imgs,
    float* __restrict__ out)
{
    const int blk   = blockIdx.x;
    const int chunk = blk % CHUNKS_PER_SLICE_;
    const int slice = blk / CHUNKS_PER_SLICE_;

    const Desc d = g_desc[slice];           // single 8B load, L2-hot
    const float s = d.s;

    const float4* __restrict__ src =
        reinterpret_cast<const float4*>(imgs + (size_t)d.off)
        + (size_t)chunk * (CHUNK_ / 4) + threadIdx.x;
    float4* __restrict__ dst =
        reinterpret_cast<float4*>(out) + (size_t)slice * (HW_ / 4)
        + (size_t)chunk * (CHUNK_ / 4) + threadIdx.x;

    // Front-batched loads: volatile asm pins issue order -> 8 LDG.128 in flight.
    float4 v[VEC_ITERS_];
#pragma unroll
    for (int i = 0; i < VEC_ITERS_; i++) {
        asm volatile("ld.global.nc.v4.f32 {%0,%1,%2,%3}, [%4];"
                     : "=f"(v[i].x), "=f"(v[i].y), "=f"(v[i].z), "=f"(v[i].w)
                     : "l"(src + i * THREADS_));
    }

#pragma unroll
    for (int i = 0; i < VEC_ITERS_; i++) {
        float4 r = v[i];
        r.x *= s; r.y *= s; r.z *= s; r.w *= s;
        dst[i * THREADS_] = r;
    }
}

extern "C" void kernel_launch(void* const* d_in, const int* in_sizes, int n_in,
                              void* d_out, int out_size)
{
    const float* imgs = (const float*)d_in[0];
    const float* wts  = (const float*)d_in[1];
    float* out        = (float*)d_out;

    mt2v_desc_kernel<<<(NSLICE_ + 223) / 224, 224>>>(wts);
    mt2v_gather_kernel<<<NSLICE_ * CHUNKS_PER_SLICE_, THREADS_>>>(imgs, out);
}